// round 8
// baseline (speedup 1.0000x reference)
#include <cuda_runtime.h>
#include <cuda_bf16.h>
#include <mma.h>
#include <math.h>
#include <stdint.h>

using namespace nvcuda;

#define BB 2
#define SS 2048
#define DM 1024
#define NH 16
#define FF 4096
#define MT (BB*SS)   // 4096 rows

// ===================== packed f32x2 helpers (attention) =====================
union F2U { unsigned long long u; float2 f; };
__device__ __forceinline__ void fma2(F2U& d, const F2U a, const F2U b) {
    asm("fma.rn.f32x2 %0, %1, %2, %0;" : "+l"(d.u) : "l"(a.u), "l"(b.u));
}

__device__ __forceinline__ uint32_t smem_to_u32(const void* p) {
    uint32_t a;
    asm("{ .reg .u64 tmp; cvta.to.shared.u64 tmp, %1; cvt.u32.u64 %0, tmp; }" : "=r"(a) : "l"(p));
    return a;
}
#define CP_ASYNC16(dst, src) \
    asm volatile("cp.async.cg.shared.global [%0], [%1], 16;" :: "r"(dst), "l"(src))
#define CP_COMMIT() asm volatile("cp.async.commit_group;" ::: "memory")
#define CP_WAIT1()  asm volatile("cp.async.wait_group 1;"  ::: "memory")
#define CP_WAIT0()  asm volatile("cp.async.wait_group 0;"  ::: "memory")

// ===================== scratch =====================
__device__ float g_h1[MT*DM];
__device__ float g_q[MT*DM], g_k[MT*DM], g_v[MT*DM];
__device__ float g_cat[MT*DM];
__device__ float g_attx[MT*DM];
__device__ float g_h2[MT*DM];
__device__ float g_ff1[(size_t)MT*FF];

// ===================== LayerNorm (fp32) =====================
__global__ void ln_kernel(const float* __restrict__ x, const float* __restrict__ w,
                          const float* __restrict__ b, float* __restrict__ out) {
    int row = blockIdx.x;
    int t = threadIdx.x;                       // 256 threads x 4 floats
    const float4* xr = (const float4*)(x + (size_t)row * DM);
    float4 v = xr[t];
    float s  = v.x + v.y + v.z + v.w;
    float ss = v.x*v.x + v.y*v.y + v.z*v.z + v.w*v.w;
    #pragma unroll
    for (int o = 16; o; o >>= 1) {
        s  += __shfl_xor_sync(0xffffffffu, s,  o);
        ss += __shfl_xor_sync(0xffffffffu, ss, o);
    }
    __shared__ float red[2][8];
    __shared__ float stats[2];
    int lane = t & 31, wid = t >> 5;
    if (lane == 0) { red[0][wid] = s; red[1][wid] = ss; }
    __syncthreads();
    if (t == 0) {
        float S1 = 0.f, S2 = 0.f;
        #pragma unroll
        for (int i = 0; i < 8; i++) { S1 += red[0][i]; S2 += red[1][i]; }
        float mu  = S1 * (1.f / DM);
        float var = S2 * (1.f / DM) - mu * mu;
        stats[0] = mu; stats[1] = rsqrtf(var + 1e-5f);
    }
    __syncthreads();
    float mu = stats[0], rs = stats[1];
    float4 wv = ((const float4*)w)[t];
    float4 bv = ((const float4*)b)[t];
    float4 o4;
    o4.x = (v.x - mu) * rs * wv.x + bv.x;
    o4.y = (v.y - mu) * rs * wv.y + bv.y;
    o4.z = (v.z - mu) * rs * wv.z + bv.z;
    o4.w = (v.w - mu) * rs * wv.w + bv.w;
    ((float4*)(out + (size_t)row * DM))[t] = o4;
}

// ===================== tf32 wmma GEMM =====================
// D[M,N] = A[M,K] * B[K,N], single-term tf32, fp32 accum.
// CTA tile 128x128, 4 warps of 64x64, BK=32, 2-stage cp.async.
// BMODE: 0 = B row-major [K,N] (ldB=N); 1 = headed QKV: 3 weight ptrs [H,1024,64]
// EPI:   0 = QKV scatter -> q/k/v [b,h,s,e]; 1 = +resid; 2 = +bias exact GELU; 3 = +bias+resid
#define APITCH 36                 // floats (A tile 128 x 32, pitch 36)
#define BPITCH 132                // floats (B tile 32 x 128, pitch 132)
#define ATILE  (128*APITCH*4)     // 18432 B
#define BTILE  (32*BPITCH*4)      // 16896 B
#define STAGEB (ATILE + BTILE)    // 35328 B
#define GSMEM  (2*STAGEB)         // 70656 B (epilogue 128*132*4 = 67584 fits)

template<int BMODE, int EPI>
__global__ __launch_bounds__(128, 2)
void gemmt(const float* __restrict__ A,
           const float* __restrict__ Bm, const float* __restrict__ Bm2, const float* __restrict__ Bm3,
           int K,
           float* __restrict__ out0, float* __restrict__ out1, float* __restrict__ out2,
           const float* __restrict__ bias, const float* __restrict__ resid, int N)
{
    extern __shared__ __align__(16) uint8_t smraw[];
    const uint32_t smb = smem_to_u32(smraw);
    const int tid = threadIdx.x;
    const int wid = tid >> 5;
    const int wm = wid >> 1, wn = wid & 1;     // 2x2 warp grid, 64x64 each
    const int m0 = blockIdx.y * 128;
    const int n0 = blockIdx.x * 128;

    // resolve headed-B base (BMODE 1): cols n0..n0+127 = heads h0,h0+1 of proj p
    const float* Bbase = Bm;
    if (BMODE == 1) {
        int proj = n0 >> 10;
        Bbase = (proj == 0) ? Bm : (proj == 1) ? Bm2 : Bm3;
    }

    wmma::fragment<wmma::accumulator, 16, 16, 8, float> acc[4][4];
    #pragma unroll
    for (int i = 0; i < 4; i++)
        #pragma unroll
        for (int j = 0; j < 4; j++) wmma::fill_fragment(acc[i][j], 0.0f);

    const int NCH = K >> 5;

    // async load of chunk ch into stage st: A 128x32 (1024 x 16B), B 32x128 (1024 x 16B)
    auto issue = [&](int ch, int st) {
        int k0 = ch << 5;
        uint32_t sa = smb + st * STAGEB;
        uint32_t sb = sa + ATILE;
        #pragma unroll
        for (int i = 0; i < 8; i++) {          // A: idx = row*8 + chunk
            int idx = i * 128 + tid;
            int r = idx >> 3, c = idx & 7;
            uint32_t dst = sa + (uint32_t)(r * APITCH + c * 4) * 4;
            const float* src = A + (size_t)(m0 + r) * K + k0 + c * 4;
            CP_ASYNC16(dst, src);
        }
        #pragma unroll
        for (int i = 0; i < 8; i++) {          // B: idx = row*32 + chunk
            int idx = i * 128 + tid;
            int r = idx >> 5, c = idx & 31;    // r 0..31, col = c*4
            uint32_t dst = sb + (uint32_t)(r * BPITCH + c * 4) * 4;
            const float* src;
            if (BMODE == 0) {
                src = Bm + (size_t)(k0 + r) * N + n0 + c * 4;
            } else {
                int col = c * 4;
                int hsel = col >> 6;           // 0 or 1
                int e = col & 63;
                int h = ((n0 & 1023) >> 6) + hsel;
                src = Bbase + ((size_t)h * 1024 + (k0 + r)) * 64 + e;
            }
            CP_ASYNC16(dst, src);
        }
        CP_COMMIT();
    };

    issue(0, 0);

    for (int ch = 0; ch < NCH; ch++) {
        if (ch + 1 < NCH) { issue(ch + 1, (ch + 1) & 1); CP_WAIT1(); }
        else              { CP_WAIT0(); }
        __syncthreads();
        const int st = ch & 1;
        const float* As = (const float*)(smraw + st * STAGEB);
        const float* Bs = (const float*)(smraw + st * STAGEB + ATILE);
        #pragma unroll
        for (int kk = 0; kk < 32; kk += 8) {
            wmma::fragment<wmma::matrix_a, 16, 16, 8, wmma::precision::tf32, wmma::row_major> af[4];
            #pragma unroll
            for (int i = 0; i < 4; i++) {
                wmma::load_matrix_sync(af[i], As + (wm * 64 + i * 16) * APITCH + kk, APITCH);
                #pragma unroll
                for (int e = 0; e < af[i].num_elements; e++)
                    af[i].x[e] = wmma::__float_to_tf32(af[i].x[e]);
            }
            #pragma unroll
            for (int j = 0; j < 4; j++) {
                wmma::fragment<wmma::matrix_b, 16, 16, 8, wmma::precision::tf32, wmma::row_major> bf;
                wmma::load_matrix_sync(bf, Bs + kk * BPITCH + wn * 64 + j * 16, BPITCH);
                #pragma unroll
                for (int e = 0; e < bf.num_elements; e++)
                    bf.x[e] = wmma::__float_to_tf32(bf.x[e]);
                #pragma unroll
                for (int i = 0; i < 4; i++)
                    wmma::mma_sync(acc[i][j], af[i], bf, acc[i][j]);
            }
        }
        __syncthreads();
    }

    // ---- epilogue through smem for coalesced writes ----
    float* Cs = (float*)smraw;        // [128][132]
    #pragma unroll
    for (int i = 0; i < 4; i++)
        #pragma unroll
        for (int j = 0; j < 4; j++)
            wmma::store_matrix_sync(Cs + (wm * 64 + i * 16) * 132 + (wn * 64 + j * 16),
                                    acc[i][j], 132, wmma::mem_row_major);
    __syncthreads();

    #pragma unroll
    for (int it = 0; it < 32; it++) {
        int idx = it * 128 + tid;
        int r  = idx >> 5;
        int c4 = (idx & 31) << 2;
        float4 vv = *(const float4*)(Cs + r * 132 + c4);
        int row = m0 + r;
        int c   = n0 + c4;
        if (EPI == 0) {
            int b = row >> 11, sq = row & 2047;
            int proj = c >> 10, cc = c & 1023, hh = cc >> 6, e0 = cc & 63;
            float* base = (proj == 0) ? out0 : (proj == 1) ? out1 : out2;
            *(float4*)(base + ((size_t)(b * NH + hh) * SS + sq) * 64 + e0) = vv;
        } else if (EPI == 1) {
            float4 r4 = *(const float4*)(resid + (size_t)row * N + c);
            vv.x += r4.x; vv.y += r4.y; vv.z += r4.z; vv.w += r4.w;
            *(float4*)(out0 + (size_t)row * N + c) = vv;
        } else if (EPI == 2) {
            float4 b4 = *(const float4*)(bias + c);
            vv.x += b4.x; vv.y += b4.y; vv.z += b4.z; vv.w += b4.w;
            vv.x = 0.5f * vv.x * (1.f + erff(vv.x * 0.70710678118f));
            vv.y = 0.5f * vv.y * (1.f + erff(vv.y * 0.70710678118f));
            vv.z = 0.5f * vv.z * (1.f + erff(vv.z * 0.70710678118f));
            vv.w = 0.5f * vv.w * (1.f + erff(vv.w * 0.70710678118f));
            *(float4*)(out0 + (size_t)row * N + c) = vv;
        } else {  // EPI == 3
            float4 b4 = *(const float4*)(bias + c);
            float4 r4 = *(const float4*)(resid + (size_t)row * N + c);
            vv.x += b4.x + r4.x; vv.y += b4.y + r4.y;
            vv.z += b4.z + r4.z; vv.w += b4.w + r4.w;
            *(float4*)(out0 + (size_t)row * N + c) = vv;
        }
    }
}

// ===================== causal flash attention (fp32, f32x2) =====================
__global__ void attn_kernel(const float* __restrict__ Q, const float* __restrict__ Kg,
                            const float* __restrict__ Vg, float* __restrict__ Out)
{
    __shared__ __align__(16) float KV[64][64];
    __shared__ float sc[64][65];
    int t  = threadIdx.x;
    int qt = blockIdx.x;
    int bh = blockIdx.y;
    int qi = qt * 64 + t;

    const float* qrow = Q + ((size_t)bh * SS + qi) * 64;
    F2U qp[32];
    #pragma unroll
    for (int e = 0; e < 32; e += 2) {
        float4 f = *(const float4*)(qrow + 2 * e);
        qp[e].f     = make_float2(f.x, f.y);
        qp[e + 1].f = make_float2(f.z, f.w);
    }
    F2U accp[32];
    #pragma unroll
    for (int e = 0; e < 32; e++) accp[e].u = 0ull;
    float m = -INFINITY, l = 0.f;

    for (int kt = 0; kt <= qt; kt++) {
        int k0 = kt * 64;
        __syncthreads();
        const float* kb = Kg + ((size_t)bh * SS + k0) * 64;
        for (int i = t; i < 64 * 16; i += 64) {
            int r = i >> 4, c = (i & 15) << 2;
            *(float4*)&KV[r][c] = *(const float4*)(kb + r * 64 + c);
        }
        __syncthreads();

        float tmax = -INFINITY;
        for (int j = 0; j < 64; j++) {
            const F2U* kr = (const F2U*)KV[j];
            F2U s2; s2.u = 0ull;
            #pragma unroll
            for (int e = 0; e < 32; e++) fma2(s2, qp[e], kr[e]);
            float s = (s2.f.x + s2.f.y) * 0.125f;
            if (k0 + j > qi) s = -INFINITY;
            sc[t][j] = s;
            tmax = fmaxf(tmax, s);
        }
        float nm   = fmaxf(m, tmax);
        float corr = __expf(m - nm);
        l *= corr;
        #pragma unroll
        for (int e = 0; e < 32; e++) { accp[e].f.x *= corr; accp[e].f.y *= corr; }

        __syncthreads();
        const float* vb = Vg + ((size_t)bh * SS + k0) * 64;
        for (int i = t; i < 64 * 16; i += 64) {
            int r = i >> 4, c = (i & 15) << 2;
            *(float4*)&KV[r][c] = *(const float4*)(vb + r * 64 + c);
        }
        __syncthreads();

        for (int j = 0; j < 64; j++) {
            float p = __expf(sc[t][j] - nm);
            l += p;
            F2U pd; pd.f = make_float2(p, p);
            const F2U* vr = (const F2U*)KV[j];
            #pragma unroll
            for (int e = 0; e < 32; e++) fma2(accp[e], pd, vr[e]);
        }
        m = nm;
    }

    float inv = 1.f / l;
    int b = bh >> 4, hh = bh & 15;
    float* orow = Out + ((size_t)(b * SS + qi)) * DM + hh * 64;
    #pragma unroll
    for (int e = 0; e < 32; e += 2) {
        float4 f;
        f.x = accp[e].f.x * inv;     f.y = accp[e].f.y * inv;
        f.z = accp[e + 1].f.x * inv; f.w = accp[e + 1].f.y * inv;
        *(float4*)(orow + 2 * e) = f;
    }
}

// ===================== launch =====================
extern "C" void kernel_launch(void* const* d_in, const int* in_sizes, int n_in,
                              void* d_out, int out_size) {
    const float* x    = (const float*)d_in[0];
    const float* Wq   = (const float*)d_in[2];
    const float* Wk   = (const float*)d_in[3];
    const float* Wv   = (const float*)d_in[4];
    const float* Wo   = (const float*)d_in[5];
    const float* ln1w = (const float*)d_in[6];
    const float* ln1b = (const float*)d_in[7];
    const float* ln2w = (const float*)d_in[8];
    const float* ln2b = (const float*)d_in[9];
    const float* W1   = (const float*)d_in[10];
    const float* b1   = (const float*)d_in[11];
    const float* W2   = (const float*)d_in[12];
    const float* b2   = (const float*)d_in[13];
    float* out = (float*)d_out;

    float *h1, *q, *k, *v, *cat, *attx, *h2, *ff1;
    cudaGetSymbolAddress((void**)&h1,   g_h1);
    cudaGetSymbolAddress((void**)&q,    g_q);
    cudaGetSymbolAddress((void**)&k,    g_k);
    cudaGetSymbolAddress((void**)&v,    g_v);
    cudaGetSymbolAddress((void**)&cat,  g_cat);
    cudaGetSymbolAddress((void**)&attx, g_attx);
    cudaGetSymbolAddress((void**)&h2,   g_h2);
    cudaGetSymbolAddress((void**)&ff1,  g_ff1);

    cudaFuncSetAttribute(gemmt<1,0>, cudaFuncAttributeMaxDynamicSharedMemorySize, GSMEM);
    cudaFuncSetAttribute(gemmt<0,1>, cudaFuncAttributeMaxDynamicSharedMemorySize, GSMEM);
    cudaFuncSetAttribute(gemmt<0,2>, cudaFuncAttributeMaxDynamicSharedMemorySize, GSMEM);
    cudaFuncSetAttribute(gemmt<0,3>, cudaFuncAttributeMaxDynamicSharedMemorySize, GSMEM);

    // 1. LN1
    ln_kernel<<<MT, 256>>>(x, ln1w, ln1b, h1);

    // 2. QKV fused tf32 GEMM: M=4096, N=3072, K=1024 -> q/k/v [b,h,s,e]
    gemmt<1,0><<<dim3(24, 32), 128, GSMEM>>>(h1, Wq, Wk, Wv, 1024,
                                             q, k, v, nullptr, nullptr, 0);

    // 3. causal attention -> concat fp32
    attn_kernel<<<dim3(SS / 64, BB * NH), 64>>>(q, k, v, cat);

    // 4. Wo + residual(x) -> attx
    gemmt<0,1><<<dim3(8, 32), 128, GSMEM>>>(cat, Wo, nullptr, nullptr, 1024,
                                            attx, nullptr, nullptr, nullptr, x, DM);

    // 5. LN2
    ln_kernel<<<MT, 256>>>(attx, ln2w, ln2b, h2);

    // 6. FFN1 + bias + exact GELU -> ff1
    gemmt<0,2><<<dim3(32, 32), 128, GSMEM>>>(h2, W1, nullptr, nullptr, 1024,
                                             ff1, nullptr, nullptr, b1, nullptr, FF);

    // 7. FFN2 + bias + residual(attx) -> d_out
    gemmt<0,3><<<dim3(8, 32), 128, GSMEM>>>(ff1, W2, nullptr, nullptr, 4096,
                                            out, nullptr, nullptr, b2, attx, DM);
}

// round 9
// speedup vs baseline: 1.0247x; 1.0247x over previous
#include <cuda_runtime.h>
#include <cuda_bf16.h>
#include <mma.h>
#include <math.h>
#include <stdint.h>

using namespace nvcuda;

#define BB 2
#define SS 2048
#define DM 1024
#define NH 16
#define FF 4096
#define MT (BB*SS)   // 4096 rows

// ===================== helpers =====================
union F2U { unsigned long long u; float2 f; };
__device__ __forceinline__ void fma2(F2U& d, const F2U a, const F2U b) {
    asm("fma.rn.f32x2 %0, %1, %2, %0;" : "+l"(d.u) : "l"(a.u), "l"(b.u));
}
__device__ __forceinline__ float tf32r(float x) {
    float r; asm("cvt.rna.tf32.f32 %0, %1;" : "=f"(r) : "f"(x)); return r;
}
__device__ __forceinline__ uint32_t smem_to_u32(const void* p) {
    uint32_t a;
    asm("{ .reg .u64 tmp; cvta.to.shared.u64 tmp, %1; cvt.u32.u64 %0, tmp; }" : "=r"(a) : "l"(p));
    return a;
}
#define CP_ASYNC16(dst, src) \
    asm volatile("cp.async.cg.shared.global [%0], [%1], 16;" :: "r"(dst), "l"(src))
#define CP_COMMIT() asm volatile("cp.async.commit_group;" ::: "memory")
#define CP_WAIT1()  asm volatile("cp.async.wait_group 1;"  ::: "memory")
#define CP_WAIT0()  asm volatile("cp.async.wait_group 0;"  ::: "memory")

// ===================== scratch =====================
__device__ float g_h1[MT*DM];
__device__ float g_q[MT*DM], g_k[MT*DM], g_v[MT*DM];
__device__ float g_cat[MT*DM];
__device__ float g_attx[MT*DM];
__device__ float g_h2[MT*DM];
__device__ float g_ff1[(size_t)MT*FF];
// tf32-rounded weight copies (same layouts as inputs)
__device__ float g_wq[(size_t)NH*DM*64], g_wk[(size_t)NH*DM*64], g_wv[(size_t)NH*DM*64];
__device__ float g_wo[DM*DM];
__device__ float g_w1[(size_t)DM*FF];
__device__ float g_w2[(size_t)FF*DM];

// ===================== tf32 rounding pre-pass (elementwise) =====================
__global__ void round_tf32_kernel(const float* __restrict__ in, float* __restrict__ out, int n4) {
    int i = blockIdx.x * blockDim.x + threadIdx.x;
    if (i < n4) {
        float4 v = ((const float4*)in)[i];
        v.x = tf32r(v.x); v.y = tf32r(v.y); v.z = tf32r(v.z); v.w = tf32r(v.w);
        ((float4*)out)[i] = v;
    }
}

// ===================== LayerNorm (fp32 in, tf32-rounded out) =====================
__global__ void ln_kernel(const float* __restrict__ x, const float* __restrict__ w,
                          const float* __restrict__ b, float* __restrict__ out) {
    int row = blockIdx.x;
    int t = threadIdx.x;                       // 256 threads x 4 floats
    const float4* xr = (const float4*)(x + (size_t)row * DM);
    float4 v = xr[t];
    float s  = v.x + v.y + v.z + v.w;
    float ss = v.x*v.x + v.y*v.y + v.z*v.z + v.w*v.w;
    #pragma unroll
    for (int o = 16; o; o >>= 1) {
        s  += __shfl_xor_sync(0xffffffffu, s,  o);
        ss += __shfl_xor_sync(0xffffffffu, ss, o);
    }
    __shared__ float red[2][8];
    __shared__ float stats[2];
    int lane = t & 31, wid = t >> 5;
    if (lane == 0) { red[0][wid] = s; red[1][wid] = ss; }
    __syncthreads();
    if (t == 0) {
        float S1 = 0.f, S2 = 0.f;
        #pragma unroll
        for (int i = 0; i < 8; i++) { S1 += red[0][i]; S2 += red[1][i]; }
        float mu  = S1 * (1.f / DM);
        float var = S2 * (1.f / DM) - mu * mu;
        stats[0] = mu; stats[1] = rsqrtf(var + 1e-5f);
    }
    __syncthreads();
    float mu = stats[0], rs = stats[1];
    float4 wv = ((const float4*)w)[t];
    float4 bv = ((const float4*)b)[t];
    float4 o4;
    o4.x = tf32r((v.x - mu) * rs * wv.x + bv.x);
    o4.y = tf32r((v.y - mu) * rs * wv.y + bv.y);
    o4.z = tf32r((v.z - mu) * rs * wv.z + bv.z);
    o4.w = tf32r((v.w - mu) * rs * wv.w + bv.w);
    ((float4*)(out + (size_t)row * DM))[t] = o4;
}

// ===================== tf32 wmma GEMM (operands pre-rounded; no in-loop cvt) =====================
// D[M,N] = A[M,K] * B[K,N], fp32 accum.
// CTA tile 128x128, 4 warps of 64x64, BK=32, 2-stage cp.async.
// BMODE: 0 = B row-major [K,N]; 1 = headed QKV: 3 weight ptrs [H,1024,64]
// EPI:   0 = QKV scatter -> q/k/v [b,h,s,e]; 1 = +resid; 2 = +bias exact GELU (tf32-rounded out); 3 = +bias+resid
#define APITCH 36
#define BPITCH 132
#define ATILE  (128*APITCH*4)     // 18432 B
#define BTILE  (32*BPITCH*4)      // 16896 B
#define STAGEB (ATILE + BTILE)    // 35328 B
#define GSMEM  (2*STAGEB)         // 70656 B

template<int BMODE, int EPI>
__global__ __launch_bounds__(128, 2)
void gemmt(const float* __restrict__ A,
           const float* __restrict__ Bm, const float* __restrict__ Bm2, const float* __restrict__ Bm3,
           int K,
           float* __restrict__ out0, float* __restrict__ out1, float* __restrict__ out2,
           const float* __restrict__ bias, const float* __restrict__ resid, int N)
{
    extern __shared__ __align__(16) uint8_t smraw[];
    const uint32_t smb = smem_to_u32(smraw);
    const int tid = threadIdx.x;
    const int wid = tid >> 5;
    const int wm = wid >> 1, wn = wid & 1;     // 2x2 warp grid, 64x64 each
    const int m0 = blockIdx.y * 128;
    const int n0 = blockIdx.x * 128;

    const float* Bbase = Bm;
    if (BMODE == 1) {
        int proj = n0 >> 10;
        Bbase = (proj == 0) ? Bm : (proj == 1) ? Bm2 : Bm3;
    }

    wmma::fragment<wmma::accumulator, 16, 16, 8, float> acc[4][4];
    #pragma unroll
    for (int i = 0; i < 4; i++)
        #pragma unroll
        for (int j = 0; j < 4; j++) wmma::fill_fragment(acc[i][j], 0.0f);

    const int NCH = K >> 5;

    auto issue = [&](int ch, int st) {
        int k0 = ch << 5;
        uint32_t sa = smb + st * STAGEB;
        uint32_t sb = sa + ATILE;
        #pragma unroll
        for (int i = 0; i < 8; i++) {          // A: 128 rows x 2 chunks... idx = row*8+chunk
            int idx = i * 128 + tid;
            int r = idx >> 3, c = idx & 7;
            uint32_t dst = sa + (uint32_t)(r * APITCH + c * 4) * 4;
            const float* src = A + (size_t)(m0 + r) * K + k0 + c * 4;
            CP_ASYNC16(dst, src);
        }
        #pragma unroll
        for (int i = 0; i < 8; i++) {          // B: 32 rows x 32 chunks
            int idx = i * 128 + tid;
            int r = idx >> 5, c = idx & 31;
            uint32_t dst = sb + (uint32_t)(r * BPITCH + c * 4) * 4;
            const float* src;
            if (BMODE == 0) {
                src = Bm + (size_t)(k0 + r) * N + n0 + c * 4;
            } else {
                int col = c * 4;
                int hsel = col >> 6;
                int e = col & 63;
                int h = ((n0 & 1023) >> 6) + hsel;
                src = Bbase + ((size_t)h * 1024 + (k0 + r)) * 64 + e;
            }
            CP_ASYNC16(dst, src);
        }
        CP_COMMIT();
    };

    issue(0, 0);

    for (int ch = 0; ch < NCH; ch++) {
        if (ch + 1 < NCH) { issue(ch + 1, (ch + 1) & 1); CP_WAIT1(); }
        else              { CP_WAIT0(); }
        __syncthreads();
        const int st = ch & 1;
        const float* As = (const float*)(smraw + st * STAGEB);
        const float* Bs = (const float*)(smraw + st * STAGEB + ATILE);
        #pragma unroll
        for (int kk = 0; kk < 32; kk += 8) {
            wmma::fragment<wmma::matrix_a, 16, 16, 8, wmma::precision::tf32, wmma::row_major> af[4];
            #pragma unroll
            for (int i = 0; i < 4; i++)
                wmma::load_matrix_sync(af[i], As + (wm * 64 + i * 16) * APITCH + kk, APITCH);
            #pragma unroll
            for (int j = 0; j < 4; j++) {
                wmma::fragment<wmma::matrix_b, 16, 16, 8, wmma::precision::tf32, wmma::row_major> bf;
                wmma::load_matrix_sync(bf, Bs + kk * BPITCH + wn * 64 + j * 16, BPITCH);
                #pragma unroll
                for (int i = 0; i < 4; i++)
                    wmma::mma_sync(acc[i][j], af[i], bf, acc[i][j]);
            }
        }
        __syncthreads();
    }

    // ---- epilogue through smem ----
    float* Cs = (float*)smraw;        // [128][132]
    #pragma unroll
    for (int i = 0; i < 4; i++)
        #pragma unroll
        for (int j = 0; j < 4; j++)
            wmma::store_matrix_sync(Cs + (wm * 64 + i * 16) * 132 + (wn * 64 + j * 16),
                                    acc[i][j], 132, wmma::mem_row_major);
    __syncthreads();

    #pragma unroll
    for (int it = 0; it < 32; it++) {
        int idx = it * 128 + tid;
        int r  = idx >> 5;
        int c4 = (idx & 31) << 2;
        float4 vv = *(const float4*)(Cs + r * 132 + c4);
        int row = m0 + r;
        int c   = n0 + c4;
        if (EPI == 0) {
            int b = row >> 11, sq = row & 2047;
            int proj = c >> 10, cc = c & 1023, hh = cc >> 6, e0 = cc & 63;
            float* base = (proj == 0) ? out0 : (proj == 1) ? out1 : out2;
            *(float4*)(base + ((size_t)(b * NH + hh) * SS + sq) * 64 + e0) = vv;
        } else if (EPI == 1) {
            float4 r4 = *(const float4*)(resid + (size_t)row * N + c);
            vv.x += r4.x; vv.y += r4.y; vv.z += r4.z; vv.w += r4.w;
            *(float4*)(out0 + (size_t)row * N + c) = vv;
        } else if (EPI == 2) {
            float4 b4 = *(const float4*)(bias + c);
            vv.x += b4.x; vv.y += b4.y; vv.z += b4.z; vv.w += b4.w;
            vv.x = tf32r(0.5f * vv.x * (1.f + erff(vv.x * 0.70710678118f)));
            vv.y = tf32r(0.5f * vv.y * (1.f + erff(vv.y * 0.70710678118f)));
            vv.z = tf32r(0.5f * vv.z * (1.f + erff(vv.z * 0.70710678118f)));
            vv.w = tf32r(0.5f * vv.w * (1.f + erff(vv.w * 0.70710678118f)));
            *(float4*)(out0 + (size_t)row * N + c) = vv;
        } else {  // EPI == 3
            float4 b4 = *(const float4*)(bias + c);
            float4 r4 = *(const float4*)(resid + (size_t)row * N + c);
            vv.x += b4.x + r4.x; vv.y += b4.y + r4.y;
            vv.z += b4.z + r4.z; vv.w += b4.w + r4.w;
            *(float4*)(out0 + (size_t)row * N + c) = vv;
        }
    }
}

// ===================== causal flash attention (fp32, f32x2), tf32-rounded concat out =====================
__global__ void attn_kernel(const float* __restrict__ Q, const float* __restrict__ Kg,
                            const float* __restrict__ Vg, float* __restrict__ Out)
{
    __shared__ __align__(16) float KV[64][64];
    __shared__ float sc[64][65];
    int t  = threadIdx.x;
    int qt = blockIdx.x;
    int bh = blockIdx.y;
    int qi = qt * 64 + t;

    const float* qrow = Q + ((size_t)bh * SS + qi) * 64;
    F2U qp[32];
    #pragma unroll
    for (int e = 0; e < 32; e += 2) {
        float4 f = *(const float4*)(qrow + 2 * e);
        qp[e].f     = make_float2(f.x, f.y);
        qp[e + 1].f = make_float2(f.z, f.w);
    }
    F2U accp[32];
    #pragma unroll
    for (int e = 0; e < 32; e++) accp[e].u = 0ull;
    float m = -INFINITY, l = 0.f;

    for (int kt = 0; kt <= qt; kt++) {
        int k0 = kt * 64;
        __syncthreads();
        const float* kb = Kg + ((size_t)bh * SS + k0) * 64;
        for (int i = t; i < 64 * 16; i += 64) {
            int r = i >> 4, c = (i & 15) << 2;
            *(float4*)&KV[r][c] = *(const float4*)(kb + r * 64 + c);
        }
        __syncthreads();

        float tmax = -INFINITY;
        for (int j = 0; j < 64; j++) {
            const F2U* kr = (const F2U*)KV[j];
            F2U s2; s2.u = 0ull;
            #pragma unroll
            for (int e = 0; e < 32; e++) fma2(s2, qp[e], kr[e]);
            float s = (s2.f.x + s2.f.y) * 0.125f;
            if (k0 + j > qi) s = -INFINITY;
            sc[t][j] = s;
            tmax = fmaxf(tmax, s);
        }
        float nm   = fmaxf(m, tmax);
        float corr = __expf(m - nm);
        l *= corr;
        #pragma unroll
        for (int e = 0; e < 32; e++) { accp[e].f.x *= corr; accp[e].f.y *= corr; }

        __syncthreads();
        const float* vb = Vg + ((size_t)bh * SS + k0) * 64;
        for (int i = t; i < 64 * 16; i += 64) {
            int r = i >> 4, c = (i & 15) << 2;
            *(float4*)&KV[r][c] = *(const float4*)(vb + r * 64 + c);
        }
        __syncthreads();

        for (int j = 0; j < 64; j++) {
            float p = __expf(sc[t][j] - nm);
            l += p;
            F2U pd; pd.f = make_float2(p, p);
            const F2U* vr = (const F2U*)KV[j];
            #pragma unroll
            for (int e = 0; e < 32; e++) fma2(accp[e], pd, vr[e]);
        }
        m = nm;
    }

    float inv = 1.f / l;
    int b = bh >> 4, hh = bh & 15;
    float* orow = Out + ((size_t)(b * SS + qi)) * DM + hh * 64;
    #pragma unroll
    for (int e = 0; e < 32; e += 2) {
        float4 f;
        f.x = tf32r(accp[e].f.x * inv);     f.y = tf32r(accp[e].f.y * inv);
        f.z = tf32r(accp[e + 1].f.x * inv); f.w = tf32r(accp[e + 1].f.y * inv);
        *(float4*)(orow + 2 * e) = f;
    }
}

// ===================== launch =====================
extern "C" void kernel_launch(void* const* d_in, const int* in_sizes, int n_in,
                              void* d_out, int out_size) {
    const float* x    = (const float*)d_in[0];
    const float* Wq   = (const float*)d_in[2];
    const float* Wk   = (const float*)d_in[3];
    const float* Wv   = (const float*)d_in[4];
    const float* Wo   = (const float*)d_in[5];
    const float* ln1w = (const float*)d_in[6];
    const float* ln1b = (const float*)d_in[7];
    const float* ln2w = (const float*)d_in[8];
    const float* ln2b = (const float*)d_in[9];
    const float* W1   = (const float*)d_in[10];
    const float* b1   = (const float*)d_in[11];
    const float* W2   = (const float*)d_in[12];
    const float* b2   = (const float*)d_in[13];
    float* out = (float*)d_out;

    float *h1, *q, *k, *v, *cat, *attx, *h2, *ff1;
    float *wq, *wk, *wv, *wo, *w1, *w2;
    cudaGetSymbolAddress((void**)&h1,   g_h1);
    cudaGetSymbolAddress((void**)&q,    g_q);
    cudaGetSymbolAddress((void**)&k,    g_k);
    cudaGetSymbolAddress((void**)&v,    g_v);
    cudaGetSymbolAddress((void**)&cat,  g_cat);
    cudaGetSymbolAddress((void**)&attx, g_attx);
    cudaGetSymbolAddress((void**)&h2,   g_h2);
    cudaGetSymbolAddress((void**)&ff1,  g_ff1);
    cudaGetSymbolAddress((void**)&wq,   g_wq);
    cudaGetSymbolAddress((void**)&wk,   g_wk);
    cudaGetSymbolAddress((void**)&wv,   g_wv);
    cudaGetSymbolAddress((void**)&wo,   g_wo);
    cudaGetSymbolAddress((void**)&w1,   g_w1);
    cudaGetSymbolAddress((void**)&w2,   g_w2);

    cudaFuncSetAttribute(gemmt<1,0>, cudaFuncAttributeMaxDynamicSharedMemorySize, GSMEM);
    cudaFuncSetAttribute(gemmt<0,1>, cudaFuncAttributeMaxDynamicSharedMemorySize, GSMEM);
    cudaFuncSetAttribute(gemmt<0,2>, cudaFuncAttributeMaxDynamicSharedMemorySize, GSMEM);
    cudaFuncSetAttribute(gemmt<0,3>, cudaFuncAttributeMaxDynamicSharedMemorySize, GSMEM);

    // 0. round weights to tf32 (elementwise, layouts preserved)
    {
        int n1 = DM * DM / 4;           // 262144 float4 (per 1M-float matrix)
        int n4 = DM * FF / 4;           // 1048576 float4
        round_tf32_kernel<<<n1 / 256, 256>>>(Wq, wq, n1);
        round_tf32_kernel<<<n1 / 256, 256>>>(Wk, wk, n1);
        round_tf32_kernel<<<n1 / 256, 256>>>(Wv, wv, n1);
        round_tf32_kernel<<<n1 / 256, 256>>>(Wo, wo, n1);
        round_tf32_kernel<<<n4 / 256, 256>>>(W1, w1, n4);
        round_tf32_kernel<<<n4 / 256, 256>>>(W2, w2, n4);
    }

    // 1. LN1 (tf32-rounded output)
    ln_kernel<<<MT, 256>>>(x, ln1w, ln1b, h1);

    // 2. QKV fused tf32 GEMM -> q/k/v [b,h,s,e]
    gemmt<1,0><<<dim3(24, 32), 128, GSMEM>>>(h1, wq, wk, wv, 1024,
                                             q, k, v, nullptr, nullptr, 0);

    // 3. causal attention -> concat (tf32-rounded)
    attn_kernel<<<dim3(SS / 64, BB * NH), 64>>>(q, k, v, cat);

    // 4. Wo + residual(x) -> attx (exact fp32 out)
    gemmt<0,1><<<dim3(8, 32), 128, GSMEM>>>(cat, wo, nullptr, nullptr, 1024,
                                            attx, nullptr, nullptr, nullptr, x, DM);

    // 5. LN2 (tf32-rounded output)
    ln_kernel<<<MT, 256>>>(attx, ln2w, ln2b, h2);

    // 6. FFN1 + bias + exact GELU -> ff1 (tf32-rounded)
    gemmt<0,2><<<dim3(32, 32), 128, GSMEM>>>(h2, w1, nullptr, nullptr, 1024,
                                             ff1, nullptr, nullptr, b1, nullptr, FF);

    // 7. FFN2 + bias + residual(attx) -> d_out
    gemmt<0,3><<<dim3(8, 32), 128, GSMEM>>>(ff1, w2, nullptr, nullptr, 4096,
                                            out, nullptr, nullptr, b2, attx, DM);
}

// round 10
// speedup vs baseline: 1.1633x; 1.1353x over previous
#include <cuda_runtime.h>
#include <cuda_bf16.h>
#include <mma.h>
#include <math.h>
#include <stdint.h>

typedef __nv_bfloat16 bf16;
using namespace nvcuda;

#define BB 2
#define SS 2048
#define DM 1024
#define NH 16
#define FF 4096
#define MT (BB*SS)   // 4096 rows

// ===================== packed f32x2 helpers (attention) =====================
union F2U { unsigned long long u; float2 f; };
__device__ __forceinline__ void fma2(F2U& d, const F2U a, const F2U b) {
    asm("fma.rn.f32x2 %0, %1, %2, %0;" : "+l"(d.u) : "l"(a.u), "l"(b.u));
}

// ===================== split helpers =====================
__device__ __forceinline__ void split2(float v, bf16& h, bf16& l) {
    h = __float2bfloat16(v);
    l = __float2bfloat16(v - __bfloat162float(h));
}
__device__ __forceinline__ uint32_t pkb(bf16 a, bf16 b) {
    unsigned short ua = __bfloat16_as_ushort(a), ub = __bfloat16_as_ushort(b);
    return (uint32_t)ua | ((uint32_t)ub << 16);
}

__device__ __forceinline__ uint32_t smem_to_u32(const void* p) {
    uint32_t a;
    asm("{ .reg .u64 tmp; cvta.to.shared.u64 tmp, %1; cvt.u32.u64 %0, tmp; }" : "=r"(a) : "l"(p));
    return a;
}
#define CP_ASYNC16(dst, src) \
    asm volatile("cp.async.cg.shared.global [%0], [%1], 16;" :: "r"(dst), "l"(src))
#define CP_COMMIT() asm volatile("cp.async.commit_group;" ::: "memory")
#define CP_WAIT1()  asm volatile("cp.async.wait_group 1;"  ::: "memory")
#define CP_WAIT0()  asm volatile("cp.async.wait_group 0;"  ::: "memory")

// ===================== scratch =====================
__device__ bf16 g_h1a[MT*DM],  g_h1b[MT*DM];
__device__ float g_q[MT*DM], g_k[MT*DM], g_v[MT*DM];
__device__ bf16 g_cata[MT*DM], g_catb[MT*DM];
__device__ float g_attx[MT*DM];
__device__ bf16 g_h2a[MT*DM],  g_h2b[MT*DM];
__device__ bf16 g_ff1a[(size_t)MT*FF], g_ff1b[(size_t)MT*FF];
__device__ bf16 g_Wqkva[3*DM*DM], g_Wqkvb[3*DM*DM];
__device__ bf16 g_Woa[DM*DM],  g_Wob[DM*DM];
__device__ bf16 g_W1a[DM*FF],  g_W1b[DM*FF];
__device__ bf16 g_W2a[DM*FF],  g_W2b[DM*FF];

// ===================== LayerNorm -> bf16 split pair =====================
__global__ void ln_split_kernel(const float* __restrict__ x, const float* __restrict__ w,
                                const float* __restrict__ b, bf16* __restrict__ o0, bf16* __restrict__ o1) {
    int row = blockIdx.x;
    int t = threadIdx.x;                       // 256 threads x 4 floats
    const float4* xr = (const float4*)(x + (size_t)row * DM);
    float4 v = xr[t];
    float s  = v.x + v.y + v.z + v.w;
    float ss = v.x*v.x + v.y*v.y + v.z*v.z + v.w*v.w;
    #pragma unroll
    for (int o = 16; o; o >>= 1) {
        s  += __shfl_xor_sync(0xffffffffu, s,  o);
        ss += __shfl_xor_sync(0xffffffffu, ss, o);
    }
    __shared__ float red[2][8];
    __shared__ float stats[2];
    int lane = t & 31, wid = t >> 5;
    if (lane == 0) { red[0][wid] = s; red[1][wid] = ss; }
    __syncthreads();
    if (t == 0) {
        float S1 = 0.f, S2 = 0.f;
        #pragma unroll
        for (int i = 0; i < 8; i++) { S1 += red[0][i]; S2 += red[1][i]; }
        float mu  = S1 * (1.f / DM);
        float var = S2 * (1.f / DM) - mu * mu;
        stats[0] = mu; stats[1] = rsqrtf(var + 1e-5f);
    }
    __syncthreads();
    float mu = stats[0], rs = stats[1];
    float4 wv = ((const float4*)w)[t];
    float4 bv = ((const float4*)b)[t];
    float y0 = (v.x - mu) * rs * wv.x + bv.x;
    float y1 = (v.y - mu) * rs * wv.y + bv.y;
    float y2 = (v.z - mu) * rs * wv.z + bv.z;
    float y3 = (v.w - mu) * rs * wv.w + bv.w;
    bf16 h0,l0,h1,l1,h2,l2,h3,l3;
    split2(y0,h0,l0); split2(y1,h1,l1); split2(y2,h2,l2); split2(y3,h3,l3);
    size_t idx = (size_t)row * DM + t * 4;
    *(uint2*)(o0 + idx) = make_uint2(pkb(h0,h1), pkb(h2,h3));
    *(uint2*)(o1 + idx) = make_uint2(pkb(l0,l1), pkb(l2,l3));
}

// ===================== transpose + split: out[c][r] = in[r][c] (bf16 hi/lo) =====================
__global__ void tsplit_kernel(const float* __restrict__ in, bf16* __restrict__ o0, bf16* __restrict__ o1,
                              int R, int C, size_t inBatch, size_t outBatch) {
    in += (size_t)blockIdx.z * inBatch;
    o0 += (size_t)blockIdx.z * outBatch;
    o1 += (size_t)blockIdx.z * outBatch;
    __shared__ float tile[32][33];
    int c0 = blockIdx.x * 32, r0 = blockIdx.y * 32;
    int tx = threadIdx.x, ty = threadIdx.y;   // (32, 8)
    #pragma unroll
    for (int i = 0; i < 4; i++)
        tile[ty + 8*i][tx] = in[(size_t)(r0 + ty + 8*i) * C + c0 + tx];
    __syncthreads();
    #pragma unroll
    for (int i = 0; i < 4; i++) {
        float v = tile[tx][ty + 8*i];
        bf16 h, l; split2(v, h, l);
        size_t oi = (size_t)(c0 + ty + 8*i) * R + r0 + tx;
        o0[oi] = h; o1[oi] = l;
    }
}

// ===================== wmma split-bf16 GEMM v3: 8 warps x 2 CTA/SM =====================
// D[M,N] = (A0+A1)(B0+B1)^T ~= A0B0 + A0B1 + A1B0, fp32 accum.
// A row-major [M,K] bf16; B row-major [N,K] bf16 (col-major KxN view).
// CTA tile 128x128, 8 warps of 32x64, BK=32, 2-stage cp.async, 2 CTAs/SM (16 warps/SM).
// EPI: 0 = QKV scatter -> q/k/v [b,h,s,e] fp32
//      1 = +resid -> fp32 row-major
//      2 = +bias, exact GELU -> bf16 split pair
//      3 = +bias, +resid -> fp32 row-major
#define TILEB   10240              // one 128x32 bf16 tile, row pitch 80B
#define STAGEB  (4*TILEB)          // A0,A1,B0,B1
#define GSMEM   (2*STAGEB)         // 81920 B (>= 128*132*4 = 67584 epilogue)

template<int EPI>
__global__ __launch_bounds__(256, 2)
void gemmw(const bf16* __restrict__ A0, const bf16* __restrict__ A1,
           const bf16* __restrict__ B0, const bf16* __restrict__ B1, int K,
           float* __restrict__ out0, float* __restrict__ out1, float* __restrict__ out2,
           bf16* __restrict__ s0, bf16* __restrict__ s1,
           const float* __restrict__ bias, const float* __restrict__ resid, int N)
{
    extern __shared__ __align__(16) uint8_t smraw[];
    const uint32_t smb = smem_to_u32(smraw);
    const int tid = threadIdx.x;
    const int wid = tid >> 5;
    const int wm = wid >> 1, wn = wid & 1;     // 4 x 2 warp grid, 32x64 each
    const int m0 = blockIdx.y * 128;
    const int n0 = blockIdx.x * 128;

    const bf16* gsrc[4] = { A0 + (size_t)m0 * K, A1 + (size_t)m0 * K,
                            B0 + (size_t)n0 * K, B1 + (size_t)n0 * K };

    wmma::fragment<wmma::accumulator, 16, 16, 16, float> acc[2][4];
    #pragma unroll
    for (int i = 0; i < 2; i++)
        #pragma unroll
        for (int j = 0; j < 4; j++) wmma::fill_fragment(acc[i][j], 0.0f);

    const int NCH = K >> 5;

    // async load of chunk ch into stage st (4 tiles x 128 rows x 4 x 16B)
    auto issue = [&](int ch, int st) {
        int k0 = ch << 5;
        #pragma unroll
        for (int i = 0; i < 8; i++) {
            int idx = i * 256 + tid;
            int t4  = idx >> 9;
            int rem = idx & 511;
            int row = rem >> 2;
            int cch = rem & 3;
            uint32_t dst = smb + st * STAGEB + t4 * TILEB + row * 80 + cch * 16;
            const bf16* src = gsrc[t4] + (size_t)row * K + k0 + cch * 8;
            CP_ASYNC16(dst, src);
        }
        CP_COMMIT();
    };

    issue(0, 0);

    for (int ch = 0; ch < NCH; ch++) {
        if (ch + 1 < NCH) { issue(ch + 1, (ch + 1) & 1); CP_WAIT1(); }
        else              { CP_WAIT0(); }
        __syncthreads();
        const int st = ch & 1;
        const bf16* As0 = (const bf16*)(smraw + st * STAGEB);
        const bf16* As1 = (const bf16*)(smraw + st * STAGEB + TILEB);
        const bf16* Bs0 = (const bf16*)(smraw + st * STAGEB + 2 * TILEB);
        const bf16* Bs1 = (const bf16*)(smraw + st * STAGEB + 3 * TILEB);
        #pragma unroll
        for (int kk = 0; kk < 32; kk += 16) {
            wmma::fragment<wmma::matrix_a, 16, 16, 16, bf16, wmma::row_major> a0[2], a1[2];
            #pragma unroll
            for (int i = 0; i < 2; i++) {
                wmma::load_matrix_sync(a0[i], As0 + (wm * 32 + i * 16) * 40 + kk, 40);
                wmma::load_matrix_sync(a1[i], As1 + (wm * 32 + i * 16) * 40 + kk, 40);
            }
            #pragma unroll
            for (int j = 0; j < 4; j++) {
                wmma::fragment<wmma::matrix_b, 16, 16, 16, bf16, wmma::col_major> b0, b1;
                wmma::load_matrix_sync(b0, Bs0 + (wn * 64 + j * 16) * 40 + kk, 40);
                wmma::load_matrix_sync(b1, Bs1 + (wn * 64 + j * 16) * 40 + kk, 40);
                #pragma unroll
                for (int i = 0; i < 2; i++) {
                    wmma::mma_sync(acc[i][j], a0[i], b0, acc[i][j]);
                    wmma::mma_sync(acc[i][j], a0[i], b1, acc[i][j]);
                    wmma::mma_sync(acc[i][j], a1[i], b0, acc[i][j]);
                }
            }
        }
        __syncthreads();
    }

    // ---- epilogue through smem for coalesced writes ----
    float* Cs = (float*)smraw;        // [128][132]
    #pragma unroll
    for (int i = 0; i < 2; i++)
        #pragma unroll
        for (int j = 0; j < 4; j++)
            wmma::store_matrix_sync(Cs + (wm * 32 + i * 16) * 132 + (wn * 64 + j * 16),
                                    acc[i][j], 132, wmma::mem_row_major);
    __syncthreads();

    #pragma unroll
    for (int it = 0; it < 16; it++) {
        int idx = it * 256 + tid;
        int r  = idx >> 5;
        int c4 = (idx & 31) << 2;
        float4 vv = *(const float4*)(Cs + r * 132 + c4);
        int row = m0 + r;
        int c   = n0 + c4;
        if (EPI == 0) {
            int b = row >> 11, sq = row & 2047;
            int proj = c >> 10, cc = c & 1023, hh = cc >> 6, e0 = cc & 63;
            float* base = (proj == 0) ? out0 : (proj == 1) ? out1 : out2;
            *(float4*)(base + ((size_t)(b * NH + hh) * SS + sq) * 64 + e0) = vv;
        } else if (EPI == 1) {
            float4 r4 = *(const float4*)(resid + (size_t)row * N + c);
            vv.x += r4.x; vv.y += r4.y; vv.z += r4.z; vv.w += r4.w;
            *(float4*)(out0 + (size_t)row * N + c) = vv;
        } else if (EPI == 2) {
            float4 b4 = *(const float4*)(bias + c);
            float o[4] = {vv.x + b4.x, vv.y + b4.y, vv.z + b4.z, vv.w + b4.w};
            #pragma unroll
            for (int u = 0; u < 4; u++) o[u] = 0.5f * o[u] * (1.f + erff(o[u] * 0.70710678118f));
            bf16 h0,l0,h1,l1,h2,l2,h3,l3;
            split2(o[0],h0,l0); split2(o[1],h1,l1); split2(o[2],h2,l2); split2(o[3],h3,l3);
            size_t base = (size_t)row * N + c;
            *(uint2*)(s0 + base) = make_uint2(pkb(h0,h1), pkb(h2,h3));
            *(uint2*)(s1 + base) = make_uint2(pkb(l0,l1), pkb(l2,l3));
        } else {  // EPI == 3
            float4 b4 = *(const float4*)(bias + c);
            float4 r4 = *(const float4*)(resid + (size_t)row * N + c);
            vv.x += b4.x + r4.x; vv.y += b4.y + r4.y;
            vv.z += b4.z + r4.z; vv.w += b4.w + r4.w;
            *(float4*)(out0 + (size_t)row * N + c) = vv;
        }
    }
}

// ===================== causal flash attention (fp32, f32x2), writes bf16 split concat =====================
__global__ void attn_kernel(const float* __restrict__ Q, const float* __restrict__ Kg,
                            const float* __restrict__ Vg,
                            bf16* __restrict__ O0, bf16* __restrict__ O1)
{
    __shared__ __align__(16) float KV[64][64];
    __shared__ float sc[64][65];
    int t  = threadIdx.x;
    int qt = blockIdx.x;
    int bh = blockIdx.y;
    int qi = qt * 64 + t;

    const float* qrow = Q + ((size_t)bh * SS + qi) * 64;
    F2U qp[32];
    #pragma unroll
    for (int e = 0; e < 32; e += 2) {
        float4 f = *(const float4*)(qrow + 2 * e);
        qp[e].f     = make_float2(f.x, f.y);
        qp[e + 1].f = make_float2(f.z, f.w);
    }
    F2U accp[32];
    #pragma unroll
    for (int e = 0; e < 32; e++) accp[e].u = 0ull;
    float m = -INFINITY, l = 0.f;

    for (int kt = 0; kt <= qt; kt++) {
        int k0 = kt * 64;
        __syncthreads();
        const float* kb = Kg + ((size_t)bh * SS + k0) * 64;
        for (int i = t; i < 64 * 16; i += 64) {
            int r = i >> 4, c = (i & 15) << 2;
            *(float4*)&KV[r][c] = *(const float4*)(kb + r * 64 + c);
        }
        __syncthreads();

        float tmax = -INFINITY;
        for (int j = 0; j < 64; j++) {
            const F2U* kr = (const F2U*)KV[j];
            F2U s2; s2.u = 0ull;
            #pragma unroll
            for (int e = 0; e < 32; e++) fma2(s2, qp[e], kr[e]);
            float s = (s2.f.x + s2.f.y) * 0.125f;
            if (k0 + j > qi) s = -INFINITY;
            sc[t][j] = s;
            tmax = fmaxf(tmax, s);
        }
        float nm   = fmaxf(m, tmax);
        float corr = __expf(m - nm);
        l *= corr;
        #pragma unroll
        for (int e = 0; e < 32; e++) { accp[e].f.x *= corr; accp[e].f.y *= corr; }

        __syncthreads();
        const float* vb = Vg + ((size_t)bh * SS + k0) * 64;
        for (int i = t; i < 64 * 16; i += 64) {
            int r = i >> 4, c = (i & 15) << 2;
            *(float4*)&KV[r][c] = *(const float4*)(vb + r * 64 + c);
        }
        __syncthreads();

        for (int j = 0; j < 64; j++) {
            float p = __expf(sc[t][j] - nm);
            l += p;
            F2U pd; pd.f = make_float2(p, p);
            const F2U* vr = (const F2U*)KV[j];
            #pragma unroll
            for (int e = 0; e < 32; e++) fma2(accp[e], pd, vr[e]);
        }
        m = nm;
    }

    float inv = 1.f / l;
    int b = bh >> 4, hh = bh & 15;
    size_t base = ((size_t)(b * SS + qi)) * DM + hh * 64;
    #pragma unroll
    for (int e = 0; e < 32; e++) {
        float v0 = accp[e].f.x * inv, v1 = accp[e].f.y * inv;
        bf16 h0,l0,h1,l1;
        split2(v0,h0,l0); split2(v1,h1,l1);
        *(uint32_t*)(O0 + base + 2*e) = pkb(h0,h1);
        *(uint32_t*)(O1 + base + 2*e) = pkb(l0,l1);
    }
}

// ===================== launch =====================
extern "C" void kernel_launch(void* const* d_in, const int* in_sizes, int n_in,
                              void* d_out, int out_size) {
    const float* x    = (const float*)d_in[0];
    const float* Wq   = (const float*)d_in[2];
    const float* Wk   = (const float*)d_in[3];
    const float* Wv   = (const float*)d_in[4];
    const float* Wo   = (const float*)d_in[5];
    const float* ln1w = (const float*)d_in[6];
    const float* ln1b = (const float*)d_in[7];
    const float* ln2w = (const float*)d_in[8];
    const float* ln2b = (const float*)d_in[9];
    const float* W1   = (const float*)d_in[10];
    const float* b1   = (const float*)d_in[11];
    const float* W2   = (const float*)d_in[12];
    const float* b2   = (const float*)d_in[13];
    float* out = (float*)d_out;

    bf16 *h1a,*h1b,*cata,*catb,*h2a,*h2b,*ff1a,*ff1b;
    bf16 *wqkva,*wqkvb,*woa,*wob,*w1a,*w1b,*w2a,*w2b;
    float *q,*k,*v,*attx;
    cudaGetSymbolAddress((void**)&h1a, g_h1a);   cudaGetSymbolAddress((void**)&h1b, g_h1b);
    cudaGetSymbolAddress((void**)&q, g_q);       cudaGetSymbolAddress((void**)&k, g_k);
    cudaGetSymbolAddress((void**)&v, g_v);
    cudaGetSymbolAddress((void**)&cata, g_cata); cudaGetSymbolAddress((void**)&catb, g_catb);
    cudaGetSymbolAddress((void**)&attx, g_attx);
    cudaGetSymbolAddress((void**)&h2a, g_h2a);   cudaGetSymbolAddress((void**)&h2b, g_h2b);
    cudaGetSymbolAddress((void**)&ff1a, g_ff1a); cudaGetSymbolAddress((void**)&ff1b, g_ff1b);
    cudaGetSymbolAddress((void**)&wqkva, g_Wqkva); cudaGetSymbolAddress((void**)&wqkvb, g_Wqkvb);
    cudaGetSymbolAddress((void**)&woa, g_Woa);   cudaGetSymbolAddress((void**)&wob, g_Wob);
    cudaGetSymbolAddress((void**)&w1a, g_W1a);   cudaGetSymbolAddress((void**)&w1b, g_W1b);
    cudaGetSymbolAddress((void**)&w2a, g_W2a);   cudaGetSymbolAddress((void**)&w2b, g_W2b);

    cudaFuncSetAttribute(gemmw<0>, cudaFuncAttributeMaxDynamicSharedMemorySize, GSMEM);
    cudaFuncSetAttribute(gemmw<1>, cudaFuncAttributeMaxDynamicSharedMemorySize, GSMEM);
    cudaFuncSetAttribute(gemmw<2>, cudaFuncAttributeMaxDynamicSharedMemorySize, GSMEM);
    cudaFuncSetAttribute(gemmw<3>, cudaFuncAttributeMaxDynamicSharedMemorySize, GSMEM);

    dim3 t32x8(32, 8);

    // LN1 -> h1 splits
    ln_split_kernel<<<MT, 256>>>(x, ln1w, ln1b, h1a, h1b);

    // weight transpose + split (B layout: [N,K] bf16 hi/lo)
    tsplit_kernel<<<dim3(2, 32, 16), t32x8>>>(Wq, wqkva,               wqkvb,               1024, 64, (size_t)1024*64, (size_t)64*1024);
    tsplit_kernel<<<dim3(2, 32, 16), t32x8>>>(Wk, wqkva + 1024*1024,   wqkvb + 1024*1024,   1024, 64, (size_t)1024*64, (size_t)64*1024);
    tsplit_kernel<<<dim3(2, 32, 16), t32x8>>>(Wv, wqkva + 2*1024*1024, wqkvb + 2*1024*1024, 1024, 64, (size_t)1024*64, (size_t)64*1024);
    tsplit_kernel<<<dim3(32, 32, 1),  t32x8>>>(Wo, woa, wob, 1024, 1024, 0, 0);
    tsplit_kernel<<<dim3(128, 32, 1), t32x8>>>(W1, w1a, w1b, 1024, 4096, 0, 0);
    tsplit_kernel<<<dim3(32, 128, 1), t32x8>>>(W2, w2a, w2b, 4096, 1024, 0, 0);

    // QKV fused GEMM: M=4096, N=3072, K=1024 -> q/k/v fp32 [b,h,s,e]
    gemmw<0><<<dim3(24, 32), 256, GSMEM>>>(h1a, h1b, wqkva, wqkvb, 1024,
                                           q, k, v, nullptr, nullptr, nullptr, nullptr, 0);

    // causal attention -> concat bf16 splits
    attn_kernel<<<dim3(SS / 64, BB * NH), 64>>>(q, k, v, cata, catb);

    // Wo + residual(x) -> attx fp32
    gemmw<1><<<dim3(8, 32), 256, GSMEM>>>(cata, catb, woa, wob, 1024,
                                          attx, nullptr, nullptr, nullptr, nullptr, nullptr, x, DM);

    // LN2 -> h2 splits
    ln_split_kernel<<<MT, 256>>>(attx, ln2w, ln2b, h2a, h2b);

    // FFN1 + bias + GELU -> ff1 splits
    gemmw<2><<<dim3(32, 32), 256, GSMEM>>>(h2a, h2b, w1a, w1b, 1024,
                                           nullptr, nullptr, nullptr, ff1a, ff1b, b1, nullptr, FF);

    // FFN2 + bias + residual(attx) -> d_out fp32
    gemmw<3><<<dim3(8, 32), 256, GSMEM>>>(ff1a, ff1b, w2a, w2b, FF,
                                          out, nullptr, nullptr, nullptr, nullptr, b2, attx, DM);
}

// round 13
// speedup vs baseline: 1.8089x; 1.5549x over previous
#include <cuda_runtime.h>
#include <cuda_fp16.h>
#include <mma.h>
#include <math.h>
#include <stdint.h>

using namespace nvcuda;

#define BB 2
#define SS 2048
#define DM 1024
#define NH 16
#define FF 4096
#define MT (BB*SS)   // 4096 rows

// ===================== helpers =====================
union F2U { unsigned long long u; float2 f; };
__device__ __forceinline__ void fma2(F2U& d, const F2U a, const F2U b) {
    asm("fma.rn.f32x2 %0, %1, %2, %0;" : "+l"(d.u) : "l"(a.u), "l"(b.u));
}
__device__ __forceinline__ uint32_t smem_to_u32(const void* p) {
    uint32_t a;
    asm("{ .reg .u64 tmp; cvta.to.shared.u64 tmp, %1; cvt.u32.u64 %0, tmp; }" : "=r"(a) : "l"(p));
    return a;
}
#define CP_ASYNC16(dst, src) \
    asm volatile("cp.async.cg.shared.global [%0], [%1], 16;" :: "r"(dst), "l"(src))
#define CP_COMMIT() asm volatile("cp.async.commit_group;" ::: "memory")
#define CP_WAIT1()  asm volatile("cp.async.wait_group 1;"  ::: "memory")
#define CP_WAIT0()  asm volatile("cp.async.wait_group 0;"  ::: "memory")

// ===================== scratch =====================
__device__ __half g_h1h[MT*DM];
__device__ float  g_q[MT*DM], g_k[MT*DM], g_v[MT*DM];
__device__ __half g_cath[MT*DM];
__device__ float  g_attx[MT*DM];
__device__ __half g_h2h[MT*DM];
__device__ __half g_ff1h[(size_t)MT*FF];
__device__ __half g_wqkvh[3*DM*DM];       // [3072 rows N][1024 K]
__device__ __half g_woh[DM*DM];           // [1024 N][1024 K]
__device__ __half g_w1h[(size_t)DM*FF];   // [4096 N][1024 K]
__device__ __half g_w2h[(size_t)FF*DM];   // [1024 N][4096 K]

// ===================== LayerNorm fp32 -> fp16 =====================
__global__ void ln_half_kernel(const float* __restrict__ x, const float* __restrict__ w,
                               const float* __restrict__ b, __half* __restrict__ o) {
    int row = blockIdx.x;
    int t = threadIdx.x;                       // 256 threads x 4 floats
    const float4* xr = (const float4*)(x + (size_t)row * DM);
    float4 v = xr[t];
    float s  = v.x + v.y + v.z + v.w;
    float ss = v.x*v.x + v.y*v.y + v.z*v.z + v.w*v.w;
    #pragma unroll
    for (int o2 = 16; o2; o2 >>= 1) {
        s  += __shfl_xor_sync(0xffffffffu, s,  o2);
        ss += __shfl_xor_sync(0xffffffffu, ss, o2);
    }
    __shared__ float red[2][8];
    __shared__ float stats[2];
    int lane = t & 31, wid = t >> 5;
    if (lane == 0) { red[0][wid] = s; red[1][wid] = ss; }
    __syncthreads();
    if (t == 0) {
        float S1 = 0.f, S2 = 0.f;
        #pragma unroll
        for (int i = 0; i < 8; i++) { S1 += red[0][i]; S2 += red[1][i]; }
        float mu  = S1 * (1.f / DM);
        float var = S2 * (1.f / DM) - mu * mu;
        stats[0] = mu; stats[1] = rsqrtf(var + 1e-5f);
    }
    __syncthreads();
    float mu = stats[0], rs = stats[1];
    float4 wv = ((const float4*)w)[t];
    float4 bv = ((const float4*)b)[t];
    float y0 = (v.x - mu) * rs * wv.x + bv.x;
    float y1 = (v.y - mu) * rs * wv.y + bv.y;
    float y2 = (v.z - mu) * rs * wv.z + bv.z;
    float y3 = (v.w - mu) * rs * wv.w + bv.w;
    __half2 p0 = __floats2half2_rn(y0, y1);
    __half2 p1 = __floats2half2_rn(y2, y3);
    *(uint2*)(o + (size_t)row * DM + t * 4) =
        make_uint2(*(uint32_t*)&p0, *(uint32_t*)&p1);
}

// ===================== transpose fp32 [R,C] -> fp16 [C,R] =====================
__global__ void thalf_kernel(const float* __restrict__ in, __half* __restrict__ o,
                             int R, int C, size_t inBatch, size_t outBatch) {
    in += (size_t)blockIdx.z * inBatch;
    o  += (size_t)blockIdx.z * outBatch;
    __shared__ float tile[32][33];
    int c0 = blockIdx.x * 32, r0 = blockIdx.y * 32;
    int tx = threadIdx.x, ty = threadIdx.y;   // (32, 8)
    #pragma unroll
    for (int i = 0; i < 4; i++)
        tile[ty + 8*i][tx] = in[(size_t)(r0 + ty + 8*i) * C + c0 + tx];
    __syncthreads();
    #pragma unroll
    for (int i = 0; i < 4; i++) {
        float v = tile[tx][ty + 8*i];
        o[(size_t)(c0 + ty + 8*i) * R + r0 + tx] = __float2half_rn(v);
    }
}

// ===================== fp16 single-term wmma GEMM =====================
// D[M,N] = A[M,K] * B[N,K]^T, fp16 operands (pre-rounded), fp32 accum.
// CTA tile 128x128, 4 warps of 64x64, BK=32, 3-stage cp.async, 2 CTAs/SM.
// EPI: 0 = QKV scatter -> q/k/v [b,h,s,e] fp32
//      1 = +resid -> fp32 row-major
//      2 = +bias, exact GELU -> fp16
//      3 = +bias, +resid -> fp32 row-major
#define TILEB   10240              // one 128x32 fp16 tile, row pitch 80B (40 halves)
#define STG2    (2*TILEB)          // A,B per stage = 20480
#define GSMEM   67584              // max(3*STG2=61440, epilogue 128*132*4)

template<int EPI>
__global__ __launch_bounds__(128, 2)
void gemmh(const __half* __restrict__ A, const __half* __restrict__ B, int K,
           float* __restrict__ out0, float* __restrict__ out1, float* __restrict__ out2,
           __half* __restrict__ oh,
           const float* __restrict__ bias, const float* __restrict__ resid, int N)
{
    extern __shared__ __align__(16) uint8_t smraw[];
    const uint32_t smb = smem_to_u32(smraw);
    const int tid = threadIdx.x;
    const int wid = tid >> 5;
    const int wm = wid >> 1, wn = wid & 1;     // 2x2 warp grid, 64x64 each
    const int m0 = blockIdx.y * 128;
    const int n0 = blockIdx.x * 128;

    const __half* gsrc[2] = { A + (size_t)m0 * K, B + (size_t)n0 * K };

    wmma::fragment<wmma::accumulator, 16, 16, 16, float> acc[4][4];
    #pragma unroll
    for (int i = 0; i < 4; i++)
        #pragma unroll
        for (int j = 0; j < 4; j++) wmma::fill_fragment(acc[i][j], 0.0f);

    const int NCH = K >> 5;

    // async load of chunk ch into stage st: 2 tiles x 128 rows x 4 x 16B = 1024 ops
    auto issue = [&](int ch, int st) {
        int k0 = ch << 5;
        #pragma unroll
        for (int i = 0; i < 8; i++) {
            int idx = i * 128 + tid;
            int t2  = idx >> 9;
            int rem = idx & 511;
            int row = rem >> 2;
            int cch = rem & 3;
            uint32_t dst = smb + st * STG2 + t2 * TILEB + row * 80 + cch * 16;
            const __half* src = gsrc[t2] + (size_t)row * K + k0 + cch * 8;
            CP_ASYNC16(dst, src);
        }
        CP_COMMIT();
    };

    issue(0, 0);
    if (NCH > 1) issue(1, 1);

    for (int ch = 0; ch < NCH; ch++) {
        if (ch == NCH - 1) { CP_WAIT0(); } else { CP_WAIT1(); }
        __syncthreads();
        if (ch + 2 < NCH) issue(ch + 2, (ch + 2) % 3);
        const int st = ch % 3;
        const __half* As = (const __half*)(smraw + st * STG2);
        const __half* Bs = (const __half*)(smraw + st * STG2 + TILEB);
        #pragma unroll
        for (int kk = 0; kk < 32; kk += 16) {
            wmma::fragment<wmma::matrix_a, 16, 16, 16, __half, wmma::row_major> af[4];
            #pragma unroll
            for (int i = 0; i < 4; i++)
                wmma::load_matrix_sync(af[i], As + (wm * 64 + i * 16) * 40 + kk, 40);
            #pragma unroll
            for (int j = 0; j < 4; j++) {
                wmma::fragment<wmma::matrix_b, 16, 16, 16, __half, wmma::col_major> bf;
                wmma::load_matrix_sync(bf, Bs + (wn * 64 + j * 16) * 40 + kk, 40);
                #pragma unroll
                for (int i = 0; i < 4; i++)
                    wmma::mma_sync(acc[i][j], af[i], bf, acc[i][j]);
            }
        }
    }

    // ---- epilogue through smem (reuses stage smem: sync first) ----
    __syncthreads();
    float* Cs = (float*)smraw;        // [128][132]
    #pragma unroll
    for (int i = 0; i < 4; i++)
        #pragma unroll
        for (int j = 0; j < 4; j++)
            wmma::store_matrix_sync(Cs + (wm * 64 + i * 16) * 132 + (wn * 64 + j * 16),
                                    acc[i][j], 132, wmma::mem_row_major);
    __syncthreads();

    #pragma unroll
    for (int it = 0; it < 32; it++) {
        int idx = it * 128 + tid;
        int r  = idx >> 5;
        int c4 = (idx & 31) << 2;
        float4 vv = *(const float4*)(Cs + r * 132 + c4);
        int row = m0 + r;
        int c   = n0 + c4;
        if (EPI == 0) {
            int b = row >> 11, sq = row & 2047;
            int proj = c >> 10, cc = c & 1023, hh = cc >> 6, e0 = cc & 63;
            float* base = (proj == 0) ? out0 : (proj == 1) ? out1 : out2;
            *(float4*)(base + ((size_t)(b * NH + hh) * SS + sq) * 64 + e0) = vv;
        } else if (EPI == 1) {
            float4 r4 = *(const float4*)(resid + (size_t)row * N + c);
            vv.x += r4.x; vv.y += r4.y; vv.z += r4.z; vv.w += r4.w;
            *(float4*)(out0 + (size_t)row * N + c) = vv;
        } else if (EPI == 2) {
            float4 b4 = *(const float4*)(bias + c);
            float o0 = vv.x + b4.x, o1 = vv.y + b4.y, o2 = vv.z + b4.z, o3 = vv.w + b4.w;
            o0 = 0.5f * o0 * (1.f + erff(o0 * 0.70710678118f));
            o1 = 0.5f * o1 * (1.f + erff(o1 * 0.70710678118f));
            o2 = 0.5f * o2 * (1.f + erff(o2 * 0.70710678118f));
            o3 = 0.5f * o3 * (1.f + erff(o3 * 0.70710678118f));
            __half2 p0 = __floats2half2_rn(o0, o1);
            __half2 p1 = __floats2half2_rn(o2, o3);
            *(uint2*)(oh + (size_t)row * N + c) =
                make_uint2(*(uint32_t*)&p0, *(uint32_t*)&p1);
        } else {  // EPI == 3
            float4 b4 = *(const float4*)(bias + c);
            float4 r4 = *(const float4*)(resid + (size_t)row * N + c);
            vv.x += b4.x + r4.x; vv.y += b4.y + r4.y;
            vv.z += b4.z + r4.z; vv.w += b4.w + r4.w;
            *(float4*)(out0 + (size_t)row * N + c) = vv;
        }
    }
}

// ===================== causal flash attention (fp32, f32x2) -> fp16 concat =====================
__global__ void attn_kernel(const float* __restrict__ Q, const float* __restrict__ Kg,
                            const float* __restrict__ Vg, __half* __restrict__ Oh)
{
    __shared__ __align__(16) float KV[64][64];
    __shared__ float sc[64][65];
    int t  = threadIdx.x;
    int qt = blockIdx.x;
    int bh = blockIdx.y;
    int qi = qt * 64 + t;

    const float* qrow = Q + ((size_t)bh * SS + qi) * 64;
    F2U qp[32];
    #pragma unroll
    for (int e = 0; e < 32; e += 2) {
        float4 f = *(const float4*)(qrow + 2 * e);
        qp[e].f     = make_float2(f.x, f.y);
        qp[e + 1].f = make_float2(f.z, f.w);
    }
    F2U accp[32];
    #pragma unroll
    for (int e = 0; e < 32; e++) accp[e].u = 0ull;
    float m = -INFINITY, l = 0.f;

    for (int kt = 0; kt <= qt; kt++) {
        int k0 = kt * 64;
        __syncthreads();
        const float* kb = Kg + ((size_t)bh * SS + k0) * 64;
        for (int i = t; i < 64 * 16; i += 64) {
            int r = i >> 4, c = (i & 15) << 2;
            *(float4*)&KV[r][c] = *(const float4*)(kb + r * 64 + c);
        }
        __syncthreads();

        float tmax = -INFINITY;
        for (int j = 0; j < 64; j++) {
            const F2U* kr = (const F2U*)KV[j];
            F2U s2; s2.u = 0ull;
            #pragma unroll
            for (int e = 0; e < 32; e++) fma2(s2, qp[e], kr[e]);
            float s = (s2.f.x + s2.f.y) * 0.125f;
            if (k0 + j > qi) s = -INFINITY;
            sc[t][j] = s;
            tmax = fmaxf(tmax, s);
        }
        float nm   = fmaxf(m, tmax);
        float corr = __expf(m - nm);
        l *= corr;
        #pragma unroll
        for (int e = 0; e < 32; e++) { accp[e].f.x *= corr; accp[e].f.y *= corr; }

        __syncthreads();
        const float* vb = Vg + ((size_t)bh * SS + k0) * 64;
        for (int i = t; i < 64 * 16; i += 64) {
            int r = i >> 4, c = (i & 15) << 2;
            *(float4*)&KV[r][c] = *(const float4*)(vb + r * 64 + c);
        }
        __syncthreads();

        for (int j = 0; j < 64; j++) {
            float p = __expf(sc[t][j] - nm);
            l += p;
            F2U pd; pd.f = make_float2(p, p);
            const F2U* vr = (const F2U*)KV[j];
            #pragma unroll
            for (int e = 0; e < 32; e++) fma2(accp[e], pd, vr[e]);
        }
        m = nm;
    }

    float inv = 1.f / l;
    int b = bh >> 4, hh = bh & 15;
    size_t base = ((size_t)(b * SS + qi)) * DM + hh * 64;
    #pragma unroll
    for (int e = 0; e < 32; e += 2) {
        __half2 p0 = __floats2half2_rn(accp[e].f.x * inv,     accp[e].f.y * inv);
        __half2 p1 = __floats2half2_rn(accp[e + 1].f.x * inv, accp[e + 1].f.y * inv);
        *(uint2*)(Oh + base + 2 * e) = make_uint2(*(uint32_t*)&p0, *(uint32_t*)&p1);
    }
}

// ===================== launch =====================
extern "C" void kernel_launch(void* const* d_in, const int* in_sizes, int n_in,
                              void* d_out, int out_size) {
    const float* x    = (const float*)d_in[0];
    const float* Wq   = (const float*)d_in[2];
    const float* Wk   = (const float*)d_in[3];
    const float* Wv   = (const float*)d_in[4];
    const float* Wo   = (const float*)d_in[5];
    const float* ln1w = (const float*)d_in[6];
    const float* ln1b = (const float*)d_in[7];
    const float* ln2w = (const float*)d_in[8];
    const float* ln2b = (const float*)d_in[9];
    const float* W1   = (const float*)d_in[10];
    const float* b1   = (const float*)d_in[11];
    const float* W2   = (const float*)d_in[12];
    const float* b2   = (const float*)d_in[13];
    float* out = (float*)d_out;

    __half *h1h, *cath, *h2h, *ff1h, *wqkvh, *woh, *w1h, *w2h;
    float *q, *k, *v, *attx;
    cudaGetSymbolAddress((void**)&h1h,   g_h1h);
    cudaGetSymbolAddress((void**)&q,     g_q);
    cudaGetSymbolAddress((void**)&k,     g_k);
    cudaGetSymbolAddress((void**)&v,     g_v);
    cudaGetSymbolAddress((void**)&cath,  g_cath);
    cudaGetSymbolAddress((void**)&attx,  g_attx);
    cudaGetSymbolAddress((void**)&h2h,   g_h2h);
    cudaGetSymbolAddress((void**)&ff1h,  g_ff1h);
    cudaGetSymbolAddress((void**)&wqkvh, g_wqkvh);
    cudaGetSymbolAddress((void**)&woh,   g_woh);
    cudaGetSymbolAddress((void**)&w1h,   g_w1h);
    cudaGetSymbolAddress((void**)&w2h,   g_w2h);

    cudaFuncSetAttribute(gemmh<0>, cudaFuncAttributeMaxDynamicSharedMemorySize, GSMEM);
    cudaFuncSetAttribute(gemmh<1>, cudaFuncAttributeMaxDynamicSharedMemorySize, GSMEM);
    cudaFuncSetAttribute(gemmh<2>, cudaFuncAttributeMaxDynamicSharedMemorySize, GSMEM);
    cudaFuncSetAttribute(gemmh<3>, cudaFuncAttributeMaxDynamicSharedMemorySize, GSMEM);

    dim3 t32x8(32, 8);

    // LN1 -> fp16
    ln_half_kernel<<<MT, 256>>>(x, ln1w, ln1b, h1h);

    // weight transpose -> fp16 [N,K]
    thalf_kernel<<<dim3(2, 32, 16), t32x8>>>(Wq, wqkvh,               1024, 64, (size_t)1024*64, (size_t)64*1024);
    thalf_kernel<<<dim3(2, 32, 16), t32x8>>>(Wk, wqkvh + 1024*1024,   1024, 64, (size_t)1024*64, (size_t)64*1024);
    thalf_kernel<<<dim3(2, 32, 16), t32x8>>>(Wv, wqkvh + 2*1024*1024, 1024, 64, (size_t)1024*64, (size_t)64*1024);
    thalf_kernel<<<dim3(32, 32, 1),  t32x8>>>(Wo, woh, 1024, 1024, 0, 0);
    thalf_kernel<<<dim3(128, 32, 1), t32x8>>>(W1, w1h, 1024, 4096, 0, 0);
    thalf_kernel<<<dim3(32, 128, 1), t32x8>>>(W2, w2h, 4096, 1024, 0, 0);

    // QKV fused GEMM: M=4096, N=3072, K=1024 -> q/k/v fp32 [b,h,s,e]
    gemmh<0><<<dim3(24, 32), 128, GSMEM>>>(h1h, wqkvh, 1024,
                                           q, k, v, nullptr, nullptr, nullptr, 0);

    // causal attention -> fp16 concat
    attn_kernel<<<dim3(SS / 64, BB * NH), 64>>>(q, k, v, cath);

    // Wo + residual(x) -> attx fp32
    gemmh<1><<<dim3(8, 32), 128, GSMEM>>>(cath, woh, 1024,
                                          attx, nullptr, nullptr, nullptr, nullptr, x, DM);

    // LN2 -> fp16
    ln_half_kernel<<<MT, 256>>>(attx, ln2w, ln2b, h2h);

    // FFN1 + bias + exact GELU -> fp16 ff1
    gemmh<2><<<dim3(32, 32), 128, GSMEM>>>(h2h, w1h, 1024,
                                           nullptr, nullptr, nullptr, ff1h, b1, nullptr, FF);

    // FFN2 + bias + residual(attx) -> d_out fp32
    gemmh<3><<<dim3(8, 32), 128, GSMEM>>>(ff1h, w2h, 4096,
                                          out, nullptr, nullptr, nullptr, b2, attx, DM);
}